// round 13
// baseline (speedup 1.0000x reference)
#include <cuda_runtime.h>

#define MAX_N 65536
#define NC 8                      // gather CTAs per graph

__device__ float g_p[MAX_N];      // x . w_rel  per node
__device__ float g_r[MAX_N];      // x . w_root per node
__device__ float g_svals[MAX_N];  // selected scores (k per graph)
__device__ int   g_sidx[MAX_N];   // selected local indices
__device__ float g_part[1 << 19]; // gather partials [B][NC][d]

// ---------------------------------------------------------------------------
// Kernel 1: per-node dual dot products (8 lanes/node, weights in smem).
// ---------------------------------------------------------------------------
__global__ void k_scores(const float4* __restrict__ x4,
                         const float4* __restrict__ wrel4,
                         const float4* __restrict__ wroot4,
                         int N, int d4) {
    extern __shared__ float4 wsm[];
    int t = threadIdx.x;
    for (int c = t; c < 2 * d4; c += blockDim.x)
        wsm[c] = (c < d4) ? wrel4[c] : wroot4[c - d4];
    __syncthreads();
    const float4* wa = wsm;
    const float4* wb = wsm + d4;

    int warp = (blockIdx.x * blockDim.x + t) >> 5;
    int lane = t & 31;
    int sub  = lane >> 3;
    int l8   = lane & 7;
    int node = warp * 4 + sub;
    if (node >= N) return;

    const float4* xr = x4 + (size_t)node * d4;
    float sp = 0.f, sr = 0.f;
#pragma unroll 8
    for (int c = l8; c < d4; c += 8) {
        float4 xv = xr[c];
        float4 a  = wa[c];
        float4 b  = wb[c];
        sp += xv.x * a.x + xv.y * a.y + xv.z * a.z + xv.w * a.w;
        sr += xv.x * b.x + xv.y * b.y + xv.z * b.z + xv.w * b.w;
    }
#pragma unroll
    for (int o = 4; o; o >>= 1) {
        sp += __shfl_xor_sync(0xffffffffu, sp, o);
        sr += __shfl_xor_sync(0xffffffffu, sr, o);
    }
    if (l8 == 0) {
        g_p[node] = sp;
        g_r[node] = sr;
    }
}

// ---------------------------------------------------------------------------
// Kernel 2: per-graph selection (grid B, 512 thr): smem edge aggregation,
// tanh scores, histogram exact top-k (jax tie-break, shuffle-scan suffix).
// ---------------------------------------------------------------------------
__global__ __launch_bounds__(512)
void k_select(const int* __restrict__ ei,
              const float* __restrict__ brel,
              int n, int k, int E, int Eg) {
    extern __shared__ unsigned char sm[];
    float* p_s      = (float*)sm;                       // n
    float* agg_s    = p_s + n;                          // n
    unsigned* hist  = (unsigned*)(agg_s + n);           // 256
    unsigned* wtot  = hist + 256;                       // 8
    uint2* list     = (uint2*)(wtot + 8);               // n
    int*   ctrl     = (int*)(list + n);                 // cnt, m, tb, krem

    const int g    = blockIdx.x;
    const int t    = threadIdx.x;
    const int base = g * n;
    const int nt   = blockDim.x;

    if (t < 4) ctrl[t] = 0;
    for (int b = t; b < 256; b += nt) hist[b] = 0;
    for (int i = t; i < n; i += nt) {
        p_s[i]   = g_p[base + i];
        agg_s[i] = 0.f;
    }
    __syncthreads();

    {   // edge aggregation, graph-local smem atomics
        const int eb = g * Eg;
        for (int e = t; e < Eg; e += nt) {
            int s  = ei[eb + e] - base;
            int dd = ei[E + eb + e] - base;
            atomicAdd(&agg_s[dd], p_s[s]);
        }
    }
    __syncthreads();

    // tanh score -> monotone bits (register) + bucket histogram
    unsigned myu = 0;
    if (t < n) {
        float s = tanhf(agg_s[t] + brel[0] + g_r[base + t]);
        unsigned u = __float_as_uint(s);
        myu = (u & 0x80000000u) ? ~u : (u | 0x80000000u);
        atomicAdd(&hist[myu >> 24], 1u);
    }
    __syncthreads();

    // suffix counts via warp shuffle scan
    unsigned h_b = 0, s_in = 0;
    if (t < 256) {
        h_b  = hist[t];
        s_in = h_b;
        unsigned lane = t & 31;
#pragma unroll
        for (int off = 1; off < 32; off <<= 1) {
            unsigned v = __shfl_down_sync(0xffffffffu, s_in, off);
            if (lane + off < 32) s_in += v;
        }
        if (lane == 0) wtot[t >> 5] = s_in;
    }
    __syncthreads();
    if (t < 256) {
        unsigned w = t >> 5;
        unsigned ws = 0;
        for (unsigned j = w + 1; j < 8; j++) ws += wtot[j];
        unsigned incl = s_in + ws;            // elems in buckets >= t
        unsigned excl = incl - h_b;           // elems in buckets >  t
        if (excl < (unsigned)k && (unsigned)k <= incl) {
            ctrl[2] = t;
            ctrl[3] = k - (int)excl;
        }
    }
    __syncthreads();

    const int tb   = ctrl[2];
    const int krem = ctrl[3];

    // emit clear winners; threshold bucket to fine list
    if (t < n) {
        int b = (int)(myu >> 24);
        if (b > tb) {
            int pos = atomicAdd(&ctrl[0], 1);
            unsigned fu = (myu & 0x80000000u) ? (myu & 0x7fffffffu) : ~myu;
            g_svals[g * k + pos] = __uint_as_float(fu);
            g_sidx[g * k + pos]  = t;
        } else if (b == tb) {
            int pos = atomicAdd(&ctrl[1], 1);
            list[pos] = make_uint2(myu, (unsigned)t);
        }
    }
    __syncthreads();

    // fine rank within threshold bucket (smaller index wins ties)
    {
        const int m = ctrl[1];
        if (t < m) {
            uint2 me = list[t];
            int r = 0;
            for (int l = 0; l < m; l++) {
                uint2 o = list[l];
                r += (o.x > me.x) || (o.x == me.x && o.y < me.y);
            }
            if (r < krem) {
                int pos = atomicAdd(&ctrl[0], 1);
                unsigned fu = (me.x & 0x80000000u) ? (me.x & 0x7fffffffu) : ~me.x;
                g_svals[g * k + pos] = __uint_as_float(fu);
                g_sidx[g * k + pos]  = (int)me.y;
            }
        }
    }
}

// ---------------------------------------------------------------------------
// Kernel 3: gather (grid B*NC, 256 thr). CTA (g,c) weighted-sums its slice of
// selected rows -> partial pooled vector in g_part[g][c][:].
// ~7 CTAs/SM -> memory latency fully overlapped across CTAs.
// ---------------------------------------------------------------------------
__global__ __launch_bounds__(256)
void k_gather(const float4* __restrict__ x4,
              int n, int k, int d4, int kpc) {
    extern __shared__ unsigned char sm[];
    float* sv    = (float*)sm;                 // kpc
    int*   si    = (int*)(sv + kpc);           // kpc
    float4* part = (float4*)(si + kpc);        // nrep * d4

    const int gc = blockIdx.x;
    const int g  = gc / NC;
    const int c  = gc % NC;
    const int t  = threadIdx.x;
    const int nt = blockDim.x;
    const int base = g * n;

    const int j0  = c * kpc;
    const int cnt = min(j0 + kpc, k) - j0;
    for (int j = t; j < cnt; j += nt) {
        sv[j] = g_svals[g * k + j0 + j];
        si[j] = g_sidx[g * k + j0 + j];
    }
    __syncthreads();

    const int col4 = t % d4;
    const int rep  = t / d4;
    const int nrep = nt / d4;
    const int per  = (cnt + nrep - 1) / nrep;
    const int s0   = rep * per;
    const int s1   = min(s0 + per, cnt);

    float4 a0 = {0,0,0,0}, a1 = {0,0,0,0}, a2 = {0,0,0,0}, a3 = {0,0,0,0};
    int j = s0;
    for (; j + 4 <= s1; j += 4) {
        float v0 = sv[j], v1 = sv[j+1], v2 = sv[j+2], v3 = sv[j+3];
        int   r0 = si[j], r1 = si[j+1], r2 = si[j+2], r3 = si[j+3];
        float4 q0 = x4[(size_t)(base + r0) * d4 + col4];
        float4 q1 = x4[(size_t)(base + r1) * d4 + col4];
        float4 q2 = x4[(size_t)(base + r2) * d4 + col4];
        float4 q3 = x4[(size_t)(base + r3) * d4 + col4];
        a0.x += v0*q0.x; a0.y += v0*q0.y; a0.z += v0*q0.z; a0.w += v0*q0.w;
        a1.x += v1*q1.x; a1.y += v1*q1.y; a1.z += v1*q1.z; a1.w += v1*q1.w;
        a2.x += v2*q2.x; a2.y += v2*q2.y; a2.z += v2*q2.z; a2.w += v2*q2.w;
        a3.x += v3*q3.x; a3.y += v3*q3.y; a3.z += v3*q3.z; a3.w += v3*q3.w;
    }
    for (; j < s1; j++) {
        float v = sv[j];
        float4 q = x4[(size_t)(base + si[j]) * d4 + col4];
        a0.x += v*q.x; a0.y += v*q.y; a0.z += v*q.z; a0.w += v*q.w;
    }
    float4 s;
    s.x = a0.x + a1.x + a2.x + a3.x;
    s.y = a0.y + a1.y + a2.y + a3.y;
    s.z = a0.z + a1.z + a2.z + a3.z;
    s.w = a0.w + a1.w + a2.w + a3.w;
    part[rep * d4 + col4] = s;
    __syncthreads();

    if (t < d4) {
        float4 acc = part[t];
        for (int rr = 1; rr < nrep; rr++) {
            float4 q = part[rr * d4 + t];
            acc.x += q.x; acc.y += q.y; acc.z += q.z; acc.w += q.w;
        }
        ((float4*)g_part)[(size_t)gc * d4 + t] = acc;
    }
}

// ---------------------------------------------------------------------------
// Kernel 4: per-graph (grid B, 512 thr): deterministic reduce of NC partials
// -> pooled in smem, vectorized float4 projection, add bias, write out.
// ---------------------------------------------------------------------------
__global__ __launch_bounds__(512)
void k_proj(const float* __restrict__ wproj,
            const float* __restrict__ bproj,
            float* __restrict__ out,
            int k, int d, int odim) {
    extern __shared__ unsigned char sm[];
    float*  pooled = (float*)sm;               // d
    float4* partp  = (float4*)(pooled + d);    // nrepP * od4

    const int g  = blockIdx.x;
    const int t  = threadIdx.x;
    const int nt = blockDim.x;
    const float inv_k = 1.0f / (float)k;

    if (t < d) {
        float s = 0.f;
#pragma unroll
        for (int c = 0; c < NC; c++)
            s += g_part[((size_t)g * NC + c) * d + t];
        pooled[t] = s * inv_k;
    }
    __syncthreads();

    // vectorized projection: thread -> 4 consecutive outputs, nrepP d-reps
    const int od4   = odim >> 2;               // 64
    const int o4    = t % od4;
    const int rep   = t / od4;
    const int nrepP = nt / od4;                // 8
    const int chunk = d / nrepP;               // 32
    {
        const int d0 = rep * chunk, d1 = d0 + chunk;
        const float4* w4 = (const float4*)wproj;
        float4 acc = {0, 0, 0, 0};
#pragma unroll 4
        for (int dd = d0; dd < d1; dd++) {
            float pv = pooled[dd];             // LDS broadcast
            float4 w = w4[(size_t)dd * od4 + o4];
            acc.x += pv * w.x; acc.y += pv * w.y;
            acc.z += pv * w.z; acc.w += pv * w.w;
        }
        partp[rep * od4 + o4] = acc;
    }
    __syncthreads();

    if (t < od4) {
        float4 acc = partp[t];
        for (int rr = 1; rr < nrepP; rr++) {
            float4 q = partp[rr * od4 + t];
            acc.x += q.x; acc.y += q.y; acc.z += q.z; acc.w += q.w;
        }
        float4 b = ((const float4*)bproj)[t];
        float4 o;
        o.x = acc.x + b.x; o.y = acc.y + b.y;
        o.z = acc.z + b.z; o.w = acc.w + b.w;
        ((float4*)out)[(size_t)g * od4 + t] = o;
    }
}

// ---------------------------------------------------------------------------
// Inputs: x, edge_index, batch, num_graphs, w_rel, b_rel, w_root, w_proj, b_proj.
// Output: [B, out_dim] float32.
// ---------------------------------------------------------------------------
extern "C" void kernel_launch(void* const* d_in, const int* in_sizes, int n_in,
                              void* d_out, int out_size) {
    const float* x     = (const float*)d_in[0];
    const int*   ei    = (const int*)d_in[1];
    const float* wrel  = (const float*)d_in[4];
    const float* brel  = (const float*)d_in[5];
    const float* wroot = (const float*)d_in[6];
    const float* wproj = (const float*)d_in[7];
    const float* bproj = (const float*)d_in[8];
    float* out = (float*)d_out;

    const int odim = in_sizes[8];
    const int d    = in_sizes[7] / odim;
    const int N    = in_sizes[0] / d;
    const int E    = in_sizes[1] / 2;
    const int B    = out_size / odim;
    const int n    = N / B;
    const int k    = (n + 1) / 2;       // ceil(0.5*n), RATIO = 0.5
    const int Eg   = E / B;
    const int d4   = d / 4;
    const int kpc  = (k + NC - 1) / NC; // selected rows per gather CTA

    // K1: scores
    int warps = (N + 3) / 4;
    size_t smem1 = (size_t)(2 * d4) * sizeof(float4);
    k_scores<<<(warps * 32 + 255) / 256, 256, smem1>>>(
        (const float4*)x, (const float4*)wrel, (const float4*)wroot, N, d4);

    // K2: selection
    size_t smem2 = (size_t)n * 8        // p, agg
                 + 264 * 4              // hist + wtot
                 + (size_t)n * 8        // fine list
                 + 32;                  // ctrl
    k_select<<<B, 512, smem2>>>(ei, brel, n, k, E, Eg);

    // K3: gather (NC CTAs per graph)
    const int nrep = 256 / d4;
    size_t smem3 = (size_t)kpc * 8 + (size_t)nrep * d4 * sizeof(float4);
    k_gather<<<B * NC, 256, smem3>>>((const float4*)x, n, k, d4, kpc);

    // K4: reduce + vectorized projection, one block per graph
    const int nrepP = 512 / (odim / 4);
    size_t smem4 = (size_t)d * 4 + (size_t)nrepP * (odim / 4) * 16;
    k_proj<<<B, 512, smem4>>>(wproj, bproj, out, k, d, odim);
}

// round 14
// speedup vs baseline: 1.2361x; 1.2361x over previous
#include <cuda_runtime.h>

#define MAX_N 65536
#define EPT 4   // edge pairs prefetched per thread

__device__ float g_p[MAX_N];    // x . w_rel  per node
__device__ float g_r[MAX_N];    // x . w_root per node

// ---------------------------------------------------------------------------
// Kernel 1: per-node dual dot products. 8 lanes per node (4 nodes/warp),
// weights in shared memory. (Proven: ~6.3us steady, x stays L2-resident.)
// ---------------------------------------------------------------------------
__global__ void k_scores(const float4* __restrict__ x4,
                         const float4* __restrict__ wrel4,
                         const float4* __restrict__ wroot4,
                         int N, int d4) {
    extern __shared__ float4 wsm[];
    int t = threadIdx.x;
    for (int c = t; c < 2 * d4; c += blockDim.x)
        wsm[c] = (c < d4) ? wrel4[c] : wroot4[c - d4];
    __syncthreads();
    const float4* wa = wsm;
    const float4* wb = wsm + d4;

    int warp = (blockIdx.x * blockDim.x + t) >> 5;
    int lane = t & 31;
    int sub  = lane >> 3;
    int l8   = lane & 7;
    int node = warp * 4 + sub;
    if (node >= N) return;

    const float4* xr = x4 + (size_t)node * d4;
    float sp = 0.f, sr = 0.f;
#pragma unroll 8
    for (int c = l8; c < d4; c += 8) {
        float4 xv = xr[c];
        float4 a  = wa[c];
        float4 b  = wb[c];
        sp += xv.x * a.x + xv.y * a.y + xv.z * a.z + xv.w * a.w;
        sr += xv.x * b.x + xv.y * b.y + xv.z * b.z + xv.w * b.w;
    }
#pragma unroll
    for (int o = 4; o; o >>= 1) {
        sp += __shfl_xor_sync(0xffffffffu, sp, o);
        sr += __shfl_xor_sync(0xffffffffu, sr, o);
    }
    if (l8 == 0) {
        g_p[node] = sp;
        g_r[node] = sr;
    }
}

// ---------------------------------------------------------------------------
// Kernel 2 (per-graph, 1024 threads): edge prefetch -> smem edge aggregation,
// tanh scores, histogram exact top-k (jax tie-break), deep-MLP float4 gather,
// software-pipelined vectorized projection.
// ---------------------------------------------------------------------------
__global__ __launch_bounds__(1024, 1)
void k_pool(const float* __restrict__ x,
            const int* __restrict__ ei,
            const float* __restrict__ brel,
            const float* __restrict__ wproj,
            const float* __restrict__ bproj,
            float* __restrict__ out,
            int n, int k, int d, int odim, int E, int Eg, int nrep4) {
    extern __shared__ unsigned char sm[];
    float* p_s     = (float*)sm;                                 // n
    float* agg_s   = p_s + n;                                    // n
    float* svals   = agg_s + n;                                  // k
    int*   sidx    = (int*)(svals + k);                          // k
    unsigned* hist = (unsigned*)(sidx + k);                      // 256
    unsigned* wtot = hist + 256;                                 // 8
    uint2* list    = (uint2*)(wtot + 8);                         // n
    float* part    = (float*)(list + n);                         // nrep4 * d
    float* pooled  = part + nrep4 * d;                           // d
    int*   ctrl    = (int*)(pooled + d);                         // cnt, m, tb, krem

    const int g    = blockIdx.x;
    const int t    = threadIdx.x;
    const int base = g * n;
    const int nt   = blockDim.x;
    const int d4   = d >> 2;

    // ---- prefetch: edge pairs + this thread's r + bias (all independent) ----
    int es[EPT], ed[EPT];
    {
        const int eb = g * Eg;
#pragma unroll
        for (int q = 0; q < EPT; q++) {
            int e = t + q * nt;
            if (e < Eg) {
                es[q] = ei[eb + e] - base;
                ed[q] = ei[E + eb + e] - base;
            } else { es[q] = 0; ed[q] = -1; }
        }
    }
    const float br   = brel[0];
    const float rreg = (t < n) ? g_r[base + t] : 0.f;

    if (t < 4) ctrl[t] = 0;
    for (int b = t; b < 256; b += nt) hist[b] = 0;
    for (int i = t; i < n; i += nt) {
        p_s[i]   = g_p[base + i];
        agg_s[i] = 0.f;
    }
    __syncthreads();

    // ---- edge aggregation from registers (LDS + ATOMS only) ----
    {
#pragma unroll
        for (int q = 0; q < EPT; q++)
            if (ed[q] >= 0) atomicAdd(&agg_s[ed[q]], p_s[es[q]]);
        const int eb = g * Eg;
        for (int e = EPT * nt + t; e < Eg; e += nt)
            atomicAdd(&agg_s[ei[E + eb + e] - base], p_s[ei[eb + e] - base]);
    }
    __syncthreads();

    // ---- tanh score -> monotone u32 bits (register) + bucket histogram ----
    unsigned myu = 0;
    if (t < n) {
        float s = tanhf(agg_s[t] + br + rreg);
        unsigned u = __float_as_uint(s);
        myu = (u & 0x80000000u) ? ~u : (u | 0x80000000u);
        atomicAdd(&hist[myu >> 24], 1u);
    }
    __syncthreads();

    // ---- suffix counts via warp shuffle scan ----
    unsigned h_b = 0, s_in = 0;
    if (t < 256) {
        h_b  = hist[t];
        s_in = h_b;
        unsigned lane = t & 31;
#pragma unroll
        for (int off = 1; off < 32; off <<= 1) {
            unsigned v = __shfl_down_sync(0xffffffffu, s_in, off);
            if (lane + off < 32) s_in += v;
        }
        if (lane == 0) wtot[t >> 5] = s_in;
    }
    __syncthreads();
    if (t < 256) {
        unsigned w = t >> 5;
        unsigned ws = 0;
        for (unsigned j = w + 1; j < 8; j++) ws += wtot[j];
        unsigned incl = s_in + ws;            // elems in buckets >= t
        unsigned excl = incl - h_b;           // elems in buckets >  t
        if (excl < (unsigned)k && (unsigned)k <= incl) {
            ctrl[2] = t;                      // threshold bucket
            ctrl[3] = k - (int)excl;          // take this many from it
        }
    }
    __syncthreads();

    const int tb   = ctrl[2];
    const int krem = ctrl[3];

    // ---- emit: clear winners outright; threshold bucket -> fine list ----
    if (t < n) {
        int b = (int)(myu >> 24);
        if (b > tb) {
            int pos = atomicAdd(&ctrl[0], 1);
            unsigned fu = (myu & 0x80000000u) ? (myu & 0x7fffffffu) : ~myu;
            svals[pos] = __uint_as_float(fu);
            sidx[pos]  = t;
        } else if (b == tb) {
            int pos = atomicAdd(&ctrl[1], 1);
            list[pos] = make_uint2(myu, (unsigned)t);
        }
    }
    __syncthreads();

    // ---- fine rank within threshold bucket (smaller index wins ties) ----
    {
        const int m = ctrl[1];
        if (t < m) {
            uint2 me = list[t];
            int r = 0;
            for (int l = 0; l < m; l++) {
                uint2 o = list[l];
                r += (o.x > me.x) || (o.x == me.x && o.y < me.y);
            }
            if (r < krem) {
                int pos = atomicAdd(&ctrl[0], 1);
                unsigned fu = (me.x & 0x80000000u) ? (me.x & 0x7fffffffu) : ~me.x;
                svals[pos] = __uint_as_float(fu);
                sidx[pos]  = (int)me.y;
            }
        }
    }
    __syncthreads();

    // ---- weighted mean: float4 gather, 8 loads in flight per thread ----
    {
        const int col4 = t % d4;
        const int rep  = t / d4;
        const int per  = (k + nrep4 - 1) / nrep4;
        const int j0   = rep * per;
        const int j1   = min(j0 + per, k);
        const float4* x4 = (const float4*)x;
        float4 a0 = {0,0,0,0}, a1 = {0,0,0,0}, a2 = {0,0,0,0}, a3 = {0,0,0,0};
        int j = j0;
        for (; j + 8 <= j1; j += 8) {
            float v[8]; int r[8];
#pragma unroll
            for (int u = 0; u < 8; u++) { v[u] = svals[j + u]; r[u] = sidx[j + u]; }
            float4 q[8];
#pragma unroll
            for (int u = 0; u < 8; u++)
                q[u] = x4[(size_t)(base + r[u]) * d4 + col4];
            a0.x += v[0]*q[0].x + v[4]*q[4].x; a0.y += v[0]*q[0].y + v[4]*q[4].y;
            a0.z += v[0]*q[0].z + v[4]*q[4].z; a0.w += v[0]*q[0].w + v[4]*q[4].w;
            a1.x += v[1]*q[1].x + v[5]*q[5].x; a1.y += v[1]*q[1].y + v[5]*q[5].y;
            a1.z += v[1]*q[1].z + v[5]*q[5].z; a1.w += v[1]*q[1].w + v[5]*q[5].w;
            a2.x += v[2]*q[2].x + v[6]*q[6].x; a2.y += v[2]*q[2].y + v[6]*q[6].y;
            a2.z += v[2]*q[2].z + v[6]*q[6].z; a2.w += v[2]*q[2].w + v[6]*q[6].w;
            a3.x += v[3]*q[3].x + v[7]*q[7].x; a3.y += v[3]*q[3].y + v[7]*q[7].y;
            a3.z += v[3]*q[3].z + v[7]*q[7].z; a3.w += v[3]*q[3].w + v[7]*q[7].w;
        }
        for (; j < j1; j++) {
            float v = svals[j];
            float4 q = x4[(size_t)(base + sidx[j]) * d4 + col4];
            a0.x += v*q.x; a0.y += v*q.y; a0.z += v*q.z; a0.w += v*q.w;
        }
        float4 s;
        s.x = a0.x + a1.x + a2.x + a3.x;
        s.y = a0.y + a1.y + a2.y + a3.y;
        s.z = a0.z + a1.z + a2.z + a3.z;
        s.w = a0.w + a1.w + a2.w + a3.w;
        ((float4*)part)[rep * d4 + col4] = s;
    }
    __syncthreads();

    // pooled reduce + projection-weight prefetch across the barrier
    const int od4   = odim >> 2;
    const int o4    = t % od4;
    const int prep  = t / od4;
    const int nrepP = nt / od4;            // 16
    const int chunk = d / nrepP;           // 16
    const int d0    = prep * chunk;
    const float4* w4 = (const float4*)wproj;
    float4 wpre[4];
#pragma unroll
    for (int u = 0; u < 4; u++)            // independent of pooled: issue early
        wpre[u] = w4[(size_t)(d0 + u) * od4 + o4];

    if (t < d) {
        float s = 0.f;
        for (int rr = 0; rr < nrep4; rr++) s += part[rr * d + t];
        pooled[t] = s / (float)k;
    }
    __syncthreads();

    // ---- vectorized projection (first 4 weights already in registers) ----
    {
        float4 acc = {0, 0, 0, 0};
#pragma unroll
        for (int u = 0; u < 4; u++) {
            float pv = pooled[d0 + u];
            acc.x += pv * wpre[u].x; acc.y += pv * wpre[u].y;
            acc.z += pv * wpre[u].z; acc.w += pv * wpre[u].w;
        }
#pragma unroll 4
        for (int dd = d0 + 4; dd < d0 + chunk; dd++) {
            float pv = pooled[dd];
            float4 w = w4[(size_t)dd * od4 + o4];
            acc.x += pv * w.x; acc.y += pv * w.y;
            acc.z += pv * w.z; acc.w += pv * w.w;
        }
        ((float4*)part)[prep * od4 + o4] = acc;
    }
    __syncthreads();

    if (t < od4) {
        float4 acc = ((float4*)part)[t];
        for (int rr = 1; rr < nrepP; rr++) {
            float4 q = ((float4*)part)[rr * od4 + t];
            acc.x += q.x; acc.y += q.y; acc.z += q.z; acc.w += q.w;
        }
        float4 b = ((const float4*)bproj)[t];
        float4 o;
        o.x = acc.x + b.x; o.y = acc.y + b.y;
        o.z = acc.z + b.z; o.w = acc.w + b.w;
        ((float4*)out)[(size_t)g * od4 + t] = o;
    }
}

// ---------------------------------------------------------------------------
// Inputs: x, edge_index, batch, num_graphs, w_rel, b_rel, w_root, w_proj, b_proj.
// Output: [B, out_dim] float32.
// ---------------------------------------------------------------------------
extern "C" void kernel_launch(void* const* d_in, const int* in_sizes, int n_in,
                              void* d_out, int out_size) {
    const float* x     = (const float*)d_in[0];
    const int*   ei    = (const int*)d_in[1];
    const float* wrel  = (const float*)d_in[4];
    const float* brel  = (const float*)d_in[5];
    const float* wroot = (const float*)d_in[6];
    const float* wproj = (const float*)d_in[7];
    const float* bproj = (const float*)d_in[8];
    float* out = (float*)d_out;

    const int odim = in_sizes[8];
    const int d    = in_sizes[7] / odim;
    const int N    = in_sizes[0] / d;
    const int E    = in_sizes[1] / 2;
    const int B    = out_size / odim;
    const int n    = N / B;
    const int k    = (n + 1) / 2;     // ceil(0.5 * n), RATIO = 0.5
    const int Eg   = E / B;
    const int d4   = d / 4;
    const int nrep4 = 1024 / d4;      // 16 for d=256

    // K1
    int warps = (N + 3) / 4;
    size_t smem1 = (size_t)(2 * d4) * sizeof(float4);
    k_scores<<<(warps * 32 + 255) / 256, 256, smem1>>>(
        (const float4*)x, (const float4*)wrel, (const float4*)wroot, N, d4);

    // K2
    const int pd = d > odim ? d : odim;
    size_t smem2 = (size_t)n * 8                 // p, agg
                 + (size_t)k * 8                 // svals + sidx
                 + 264 * 4                       // hist + wtot
                 + (size_t)n * 8                 // fine list
                 + (size_t)nrep4 * pd * 4        // part
                 + (size_t)d * 4                 // pooled
                 + 32;                           // ctrl + pad
    k_pool<<<B, 1024, smem2>>>(x, ei, brel, wproj, bproj, out,
                               n, k, d, odim, E, Eg, nrep4);
}